// round 7
// baseline (speedup 1.0000x reference)
#include <cuda_runtime.h>
#include <cuda_bf16.h>
#include <cuda_fp16.h>
#include <math.h>
#include <stdint.h>

#define SEQ    2048
#define BATCH  4
#define KCTX   3
#define EMBED  512
#define HIDDEN 256
#define VOCAB  32000
#define MROWS  (SEQ * BATCH)      // 8192
#define K1     (KCTX * EMBED)     // 1536

// ---------------- scratch (static device globals) ----------------
__device__ __nv_bfloat16 g_flat_hi[MROWS * K1];
__device__ __nv_bfloat16 g_flat_lo[MROWS * K1];
__device__ __nv_bfloat16 g_w1t_hi[HIDDEN * K1];     // [256][1536] K-major
__device__ __nv_bfloat16 g_w1t_lo[HIDDEN * K1];
__device__ __half        g_w2t[VOCAB * HIDDEN];     // [32000][256] K-major fp16
__device__ __half        g_h[MROWS * HIDDEN];       // [8192][256] fp16

// ---------------- helpers ----------------
__device__ __forceinline__ uint32_t smem_u32(const void* p) {
    uint32_t a;
    asm("{ .reg .u64 t; cvta.to.shared.u64 t, %1; cvt.u32.u64 %0, t; }" : "=r"(a) : "l"(p));
    return a;
}
__device__ __forceinline__ void cp16(uint32_t dst, const void* src) {
    asm volatile("cp.async.cg.shared.global [%0], [%1], 16;\n" :: "r"(dst), "l"(src));
}
__device__ __forceinline__ void cp_commit() { asm volatile("cp.async.commit_group;\n" ::: "memory"); }

#define LDSM_X4(r0, r1, r2, r3, addr) \
    asm volatile("ldmatrix.sync.aligned.m8n8.x4.shared.b16 {%0,%1,%2,%3}, [%4];" \
                 : "=r"(r0), "=r"(r1), "=r"(r2), "=r"(r3) : "r"(addr))

#define MMA_BF16(d, a, b) \
    asm volatile("mma.sync.aligned.m16n8k16.row.col.f32.bf16.bf16.f32 " \
                 "{%0,%1,%2,%3}, {%4,%5,%6,%7}, {%8,%9}, {%0,%1,%2,%3};" \
                 : "+f"((d)[0]), "+f"((d)[1]), "+f"((d)[2]), "+f"((d)[3]) \
                 : "r"((a)[0]), "r"((a)[1]), "r"((a)[2]), "r"((a)[3]), \
                   "r"((b)[0]), "r"((b)[1]))

#define MMA_F16(d, a, b) \
    asm volatile("mma.sync.aligned.m16n8k16.row.col.f32.f16.f16.f32 " \
                 "{%0,%1,%2,%3}, {%4,%5,%6,%7}, {%8,%9}, {%0,%1,%2,%3};" \
                 : "+f"((d)[0]), "+f"((d)[1]), "+f"((d)[2]), "+f"((d)[3]) \
                 : "r"((a)[0]), "r"((a)[1]), "r"((a)[2]), "r"((a)[3]), \
                   "r"((b)[0]), "r"((b)[1]))

__device__ __forceinline__ void bsplit(float x, __nv_bfloat16& hi, __nv_bfloat16& lo) {
    hi = __float2bfloat16(x);
    lo = __float2bfloat16(x - __bfloat162float(hi));
}
__device__ __forceinline__ float gelu_exact(float x) {
    return 0.5f * x * (1.0f + erff(x * 0.70710678118654752f));
}

// ---------------------------------------------------------------------------
// Gather + split (bf16 hi/lo for GEMM1)
// ---------------------------------------------------------------------------
__global__ void gather_split(const int* __restrict__ tokens, const float* __restrict__ emb) {
    int idx = blockIdx.x * blockDim.x + threadIdx.x;  // one float4
    const int Q = K1 / 4;
    if (idx >= MROWS * Q) return;
    int r = idx / Q;
    int q = idx - r * Q;
    int s = r >> 2;
    int b = r & 3;
    int g = q / (EMBED / 4);
    int e4 = q - g * (EMBED / 4);
    int pos = s + g - (KCTX - 1);
    int tok = (pos >= 0) ? tokens[pos * BATCH + b] : 0;
    float4 v = reinterpret_cast<const float4*>(emb + (size_t)tok * EMBED)[e4];
    size_t off = (size_t)r * K1 + g * EMBED + e4 * 4;
    __nv_bfloat16 h0, h1, h2, h3, l0, l1, l2, l3;
    bsplit(v.x, h0, l0); bsplit(v.y, h1, l1); bsplit(v.z, h2, l2); bsplit(v.w, h3, l3);
    *reinterpret_cast<__nv_bfloat162*>(g_flat_hi + off)     = __nv_bfloat162(h0, h1);
    *reinterpret_cast<__nv_bfloat162*>(g_flat_hi + off + 2) = __nv_bfloat162(h2, h3);
    *reinterpret_cast<__nv_bfloat162*>(g_flat_lo + off)     = __nv_bfloat162(l0, l1);
    *reinterpret_cast<__nv_bfloat162*>(g_flat_lo + off + 2) = __nv_bfloat162(l2, l3);
}

// ---------------------------------------------------------------------------
// Transpose + split (bf16 hi/lo) for W1
// ---------------------------------------------------------------------------
__global__ void transpose_split(const float* __restrict__ W,
                                __nv_bfloat16* __restrict__ Thi,
                                __nv_bfloat16* __restrict__ Tlo, int R, int C) {
    __shared__ float t[32][33];
    int c = blockIdx.x * 32 + threadIdx.x;
    int r = blockIdx.y * 32 + threadIdx.y;
    t[threadIdx.y][threadIdx.x] = W[(size_t)r * C + c];
    __syncthreads();
    int c2 = blockIdx.x * 32 + threadIdx.y;
    int r2 = blockIdx.y * 32 + threadIdx.x;
    float v = t[threadIdx.x][threadIdx.y];
    __nv_bfloat16 h, l;
    bsplit(v, h, l);
    Thi[(size_t)c2 * R + r2] = h;
    Tlo[(size_t)c2 * R + r2] = l;
}

// ---------------------------------------------------------------------------
// Transpose + fp16 for W2: W[R][C] -> T[C][R]
// ---------------------------------------------------------------------------
__global__ void transpose_f16(const float* __restrict__ W, __half* __restrict__ T,
                              int R, int C) {
    __shared__ float t[32][33];
    int c = blockIdx.x * 32 + threadIdx.x;
    int r = blockIdx.y * 32 + threadIdx.y;
    t[threadIdx.y][threadIdx.x] = W[(size_t)r * C + c];
    __syncthreads();
    int c2 = blockIdx.x * 32 + threadIdx.y;
    int r2 = blockIdx.y * 32 + threadIdx.x;
    T[(size_t)c2 * R + r2] = __float2half_rn(t[threadIdx.x][threadIdx.y]);
}

// ---------------------------------------------------------------------------
// GEMM1 (HMMA split-bf16, fused 3-phase): h = fp16(gelu(flat @ W1^T + b1))
// BM=128, BN=128, BK=32, 8 warps (2x4), warp tile 64x32.
// ---------------------------------------------------------------------------
#define NTH 256
#define RSB 80   // 32 x 16-bit (64B) + 16B pad

template <int KD, int BN_>
__global__ void __launch_bounds__(NTH, 1)
gemm_hmma(const __nv_bfloat16* __restrict__ Ahi, const __nv_bfloat16* __restrict__ Alo,
          const __nv_bfloat16* __restrict__ Bhi, const __nv_bfloat16* __restrict__ Blo,
          const float* __restrict__ bias, __half* __restrict__ outh, int N) {
    extern __shared__ char smem[];
    constexpr int NKB = KD / 32;
    constexpr int NFR = BN_ / 32;
    constexpr int NLD = NFR / 2;
    constexpr int ROWS_STAGE = 256 + 2 * BN_;
    constexpr int STAGE_B = ROWS_STAGE * RSB;
    constexpr int NI = ROWS_STAGE / 64;
    constexpr uint32_t A_LO_OFF = 128 * RSB;
    constexpr uint32_t B_HI_OFF = 256 * RSB;
    constexpr uint32_t B_LO_OFF = (256 + BN_) * RSB;

    uint32_t sb = smem_u32(smem);
    int tid = threadIdx.x;
    int wid = tid >> 5;
    int lane = tid & 31;
    int warp_m = wid & 1;
    int warp_n = wid >> 1;
    int bm = blockIdx.y * 128;
    int bn = blockIdx.x * BN_;

    float acc[4][NFR][4];
#pragma unroll
    for (int i = 0; i < 4; i++)
#pragma unroll
        for (int j = 0; j < NFR; j++)
#pragma unroll
            for (int r = 0; r < 4; r++) acc[i][j][r] = 0.0f;

    auto issue = [&](int kb) {
        int s = kb % 3;
        int koff = kb * 32;
        uint32_t base = sb + s * STAGE_B;
#pragma unroll
        for (int i = 0; i < NI; i++) {
            int li = tid + i * NTH;
            int r = li >> 2;
            int ch = li & 3;
            const __nv_bfloat16* src;
            if (i < 2)       src = Ahi + (size_t)(bm + r) * KD;
            else if (i < 4)  src = Alo + (size_t)(bm + r - 128) * KD;
            else if (i < 4 + BN_ / 64)
                             src = Bhi + (size_t)(bn + r - 256) * KD;
            else             src = Blo + (size_t)(bn + r - 256 - BN_) * KD;
            cp16(base + r * RSB + ch * 16, src + koff + ch * 8);
        }
        cp_commit();
    };

    issue(0);
    issue(1);

    int lrow = (lane & 7) + ((lane >> 3) & 1) * 8;
    int lkb = (lane >> 4) * 16;
    uint32_t a_off = (uint32_t)(warp_m * 64 + lrow) * RSB + lkb;
    uint32_t b_off = (uint32_t)(warp_n * (BN_ / 4) + lrow) * RSB + lkb;

    for (int kb = 0; kb < NKB; kb++) {
        int s = kb % 3;
        asm volatile("cp.async.wait_group 1;\n" ::: "memory");
        __syncthreads();
        if (kb + 2 < NKB) issue(kb + 2);

        uint32_t smA = sb + s * STAGE_B;
#pragma unroll
        for (int k16 = 0; k16 < 2; k16++) {
            uint32_t kb32 = k16 * 32;
            uint32_t ah[4][4], al[4][4];
#pragma unroll
            for (int fm = 0; fm < 4; fm++)
                LDSM_X4(ah[fm][0], ah[fm][1], ah[fm][2], ah[fm][3],
                        smA + a_off + fm * 16 * RSB + kb32);
#pragma unroll
            for (int fm = 0; fm < 4; fm++)
                LDSM_X4(al[fm][0], al[fm][1], al[fm][2], al[fm][3],
                        smA + A_LO_OFF + a_off + fm * 16 * RSB + kb32);

            uint32_t br[NFR][2];
#pragma unroll
            for (int fp = 0; fp < NLD; fp++) {
                uint32_t r0, r1, r2, r3;
                LDSM_X4(r0, r1, r2, r3,
                        smA + B_HI_OFF + b_off + fp * 16 * RSB + kb32);
                br[2 * fp][0] = r0; br[2 * fp][1] = r2;
                br[2 * fp + 1][0] = r1; br[2 * fp + 1][1] = r3;
            }
#pragma unroll
            for (int fm = 0; fm < 4; fm++)
#pragma unroll
                for (int fn = 0; fn < NFR; fn++)
                    MMA_BF16(acc[fm][fn], ah[fm], br[fn]);
#pragma unroll
            for (int fm = 0; fm < 4; fm++)
#pragma unroll
                for (int fn = 0; fn < NFR; fn++)
                    MMA_BF16(acc[fm][fn], al[fm], br[fn]);
#pragma unroll
            for (int fp = 0; fp < NLD; fp++) {
                uint32_t r0, r1, r2, r3;
                LDSM_X4(r0, r1, r2, r3,
                        smA + B_LO_OFF + b_off + fp * 16 * RSB + kb32);
                br[2 * fp][0] = r0; br[2 * fp][1] = r2;
                br[2 * fp + 1][0] = r1; br[2 * fp + 1][1] = r3;
            }
#pragma unroll
            for (int fm = 0; fm < 4; fm++)
#pragma unroll
                for (int fn = 0; fn < NFR; fn++)
                    MMA_BF16(acc[fm][fn], ah[fm], br[fn]);
        }
    }

    // epilogue: gelu -> fp16
    int gr = lane >> 2;
    int qc = (lane & 3) * 2;
#pragma unroll
    for (int fm = 0; fm < 4; fm++) {
        int m0 = bm + warp_m * 64 + fm * 16 + gr;
#pragma unroll
        for (int fn = 0; fn < NFR; fn++) {
            int c0 = bn + warp_n * (BN_ / 4) + fn * 8 + qc;
            float2 bv = *reinterpret_cast<const float2*>(bias + c0);
            float g00 = gelu_exact(acc[fm][fn][0] + bv.x);
            float g01 = gelu_exact(acc[fm][fn][1] + bv.y);
            float g10 = gelu_exact(acc[fm][fn][2] + bv.x);
            float g11 = gelu_exact(acc[fm][fn][3] + bv.y);
            *reinterpret_cast<__half2*>(outh + (size_t)m0 * N + c0) =
                __floats2half2_rn(g00, g01);
            *reinterpret_cast<__half2*>(outh + (size_t)(m0 + 8) * N + c0) =
                __floats2half2_rn(g10, g11);
        }
    }
}

// ---------------------------------------------------------------------------
// GEMM2 (fp16 single-phase): logits = h @ W2^T + b2.  M=8192, N=32000, K=256.
// BM=128, BN=256, BK=32, 512 threads (16 warps 4x4), warp tile 32x64.
// ---------------------------------------------------------------------------
#define NTH2 512
#define ROWS2 (128 + 256)
#define STAGE2 (ROWS2 * RSB)              // 30720
#define SMEM2 (3 * STAGE2)                // 92160
#define B_OFF2 (128 * RSB)

__global__ void __launch_bounds__(NTH2, 1)
gemm_f16(const __half* __restrict__ A, const __half* __restrict__ Bt,
         const float* __restrict__ bias, float* __restrict__ out) {
    extern __shared__ char smem[];
    constexpr int KD = HIDDEN;            // 256
    constexpr int NKB = KD / 32;          // 8
    uint32_t sb = smem_u32(smem);
    int tid = threadIdx.x;
    int wid = tid >> 5;
    int lane = tid & 31;
    int warp_m = wid & 3;                 // 0..3 (32 rows)
    int warp_n = wid >> 2;                // 0..3 (64 cols)
    int bm = blockIdx.x * 128;
    int bn = blockIdx.y * 256;

    float acc[2][8][4];
#pragma unroll
    for (int i = 0; i < 2; i++)
#pragma unroll
        for (int j = 0; j < 8; j++)
#pragma unroll
            for (int r = 0; r < 4; r++) acc[i][j][r] = 0.0f;

    auto issue = [&](int kb) {
        int s = kb % 3;
        int k0 = kb * 32;
        uint32_t base = sb + s * STAGE2;
#pragma unroll
        for (int i = 0; i < 3; i++) {
            int li = tid + i * NTH2;       // 0..1535
            int r = li >> 2;               // 0..383
            int ch = li & 3;
            const __half* src = (r < 128)
                ? A  + (size_t)(bm + r) * KD + k0 + ch * 8
                : Bt + (size_t)(bn + r - 128) * KD + k0 + ch * 8;
            cp16(base + r * RSB + ch * 16, src);
        }
        cp_commit();
    };

    issue(0);
    issue(1);

    int lrow = (lane & 7) + ((lane >> 3) & 1) * 8;
    int lkb = (lane >> 4) * 16;
    uint32_t a_off = (uint32_t)(warp_m * 32 + lrow) * RSB + lkb;
    uint32_t b_off = B_OFF2 + (uint32_t)(warp_n * 64 + lrow) * RSB + lkb;

    for (int kb = 0; kb < NKB; kb++) {
        int s = kb % 3;
        asm volatile("cp.async.wait_group 1;\n" ::: "memory");
        __syncthreads();
        if (kb + 2 < NKB) issue(kb + 2);

        uint32_t smA = sb + s * STAGE2;
#pragma unroll
        for (int k16 = 0; k16 < 2; k16++) {
            uint32_t kb32 = k16 * 32;
            uint32_t ar[2][4];
#pragma unroll
            for (int fm = 0; fm < 2; fm++)
                LDSM_X4(ar[fm][0], ar[fm][1], ar[fm][2], ar[fm][3],
                        smA + a_off + fm * 16 * RSB + kb32);
            uint32_t br[8][2];
#pragma unroll
            for (int fp = 0; fp < 4; fp++) {
                uint32_t r0, r1, r2, r3;
                LDSM_X4(r0, r1, r2, r3,
                        smA + b_off + fp * 16 * RSB + kb32);
                br[2 * fp][0] = r0; br[2 * fp][1] = r2;
                br[2 * fp + 1][0] = r1; br[2 * fp + 1][1] = r3;
            }
#pragma unroll
            for (int fm = 0; fm < 2; fm++)
#pragma unroll
                for (int fn = 0; fn < 8; fn++)
                    MMA_F16(acc[fm][fn], ar[fm], br[fn]);
        }
    }

    // epilogue
    int gr = lane >> 2;
    int qc = (lane & 3) * 2;
#pragma unroll
    for (int fm = 0; fm < 2; fm++) {
        int m0 = bm + warp_m * 32 + fm * 16 + gr;
#pragma unroll
        for (int fn = 0; fn < 8; fn++) {
            int c0 = bn + warp_n * 64 + fn * 8 + qc;
            float2 bv = *reinterpret_cast<const float2*>(bias + c0);
            *reinterpret_cast<float2*>(out + (size_t)m0 * VOCAB + c0) =
                make_float2(acc[fm][fn][0] + bv.x, acc[fm][fn][1] + bv.y);
            *reinterpret_cast<float2*>(out + (size_t)(m0 + 8) * VOCAB + c0) =
                make_float2(acc[fm][fn][2] + bv.x, acc[fm][fn][3] + bv.y);
        }
    }
}

// ---------------------------------------------------------------------------
extern "C" void kernel_launch(void* const* d_in, const int* in_sizes, int n_in,
                              void* d_out, int out_size) {
    const int*   tokens = (const int*)  d_in[0];
    const float* emb    = (const float*)d_in[1];
    const float* W1     = (const float*)d_in[2];
    const float* b1     = (const float*)d_in[3];
    const float* W2     = (const float*)d_in[4];
    const float* b2     = (const float*)d_in[5];
    float* out = (float*)d_out;

    __nv_bfloat16 *fh, *fl, *w1h, *w1l;
    __half *w2t, *hp;
    cudaGetSymbolAddress((void**)&fh,  g_flat_hi);
    cudaGetSymbolAddress((void**)&fl,  g_flat_lo);
    cudaGetSymbolAddress((void**)&w1h, g_w1t_hi);
    cudaGetSymbolAddress((void**)&w1l, g_w1t_lo);
    cudaGetSymbolAddress((void**)&w2t, g_w2t);
    cudaGetSymbolAddress((void**)&hp,  g_h);

    constexpr int SMEM1 = 3 * (256 + 2 * 128) * RSB;   // 122880
    cudaFuncSetAttribute(gemm_hmma<K1, 128>,
                         cudaFuncAttributeMaxDynamicSharedMemorySize, SMEM1);
    cudaFuncSetAttribute(gemm_f16,
                         cudaFuncAttributeMaxDynamicSharedMemorySize, SMEM2);

    // 1) gather + split (bf16 hi/lo)
    {
        int total4 = MROWS * (K1 / 4);
        gather_split<<<(total4 + 255) / 256, 256>>>(tokens, emb);
    }
    // 2) weight prep
    {
        dim3 blk(32, 32);
        transpose_split<<<dim3(HIDDEN / 32, K1 / 32), blk>>>(W1, w1h, w1l, K1, HIDDEN);
        transpose_f16<<<dim3(VOCAB / 32, HIDDEN / 32), blk>>>(W2, w2t, HIDDEN, VOCAB);
    }
    // 3) h = fp16(gelu(flat @ W1 + b1))   (M=8192, N=256, K=1536)
    {
        dim3 grid(HIDDEN / 128, MROWS / 128);   // (2, 64)
        gemm_hmma<K1, 128><<<grid, NTH, SMEM1>>>(fh, fl, w1h, w1l, b1, hp, HIDDEN);
    }
    // 4) logits = h @ W2 + b2   (M=8192, N=32000, K=256), fp16 HMMA
    {
        dim3 grid(MROWS / 128, VOCAB / 256);    // (64, 125)
        gemm_f16<<<grid, NTH2, SMEM2>>>(hp, w2t, b2, out);
    }
}

// round 9
// speedup vs baseline: 1.0568x; 1.0568x over previous
#include <cuda_runtime.h>
#include <cuda_fp16.h>
#include <math.h>
#include <stdint.h>

#define SEQ    2048
#define BATCH  4
#define KCTX   3
#define EMBED  512
#define HIDDEN 256
#define VOCAB  32000
#define MROWS  (SEQ * BATCH)      // 8192
#define K1     (KCTX * EMBED)     // 1536

// ---------------- scratch (static device globals) ----------------
__device__ __half g_flat[MROWS * K1];      // [8192][1536] fp16
__device__ __half g_w1t[HIDDEN * K1];      // [256][1536] K-major fp16
__device__ __half g_w2t[VOCAB * HIDDEN];   // [32000][256] K-major fp16
__device__ __half g_h[MROWS * HIDDEN];     // [8192][256] fp16

// ---------------- helpers ----------------
__device__ __forceinline__ uint32_t smem_u32(const void* p) {
    uint32_t a;
    asm("{ .reg .u64 t; cvta.to.shared.u64 t, %1; cvt.u32.u64 %0, t; }" : "=r"(a) : "l"(p));
    return a;
}
__device__ __forceinline__ void cp16(uint32_t dst, const void* src) {
    asm volatile("cp.async.cg.shared.global [%0], [%1], 16;\n" :: "r"(dst), "l"(src));
}
__device__ __forceinline__ void cp_commit() { asm volatile("cp.async.commit_group;\n" ::: "memory"); }

#define LDSM_X4(r0, r1, r2, r3, addr) \
    asm volatile("ldmatrix.sync.aligned.m8n8.x4.shared.b16 {%0,%1,%2,%3}, [%4];" \
                 : "=r"(r0), "=r"(r1), "=r"(r2), "=r"(r3) : "r"(addr))

#define MMA_F16(d, a, b) \
    asm volatile("mma.sync.aligned.m16n8k16.row.col.f32.f16.f16.f32 " \
                 "{%0,%1,%2,%3}, {%4,%5,%6,%7}, {%8,%9}, {%0,%1,%2,%3};" \
                 : "+f"((d)[0]), "+f"((d)[1]), "+f"((d)[2]), "+f"((d)[3]) \
                 : "r"((a)[0]), "r"((a)[1]), "r"((a)[2]), "r"((a)[3]), \
                   "r"((b)[0]), "r"((b)[1]))

__device__ __forceinline__ float gelu_exact(float x) {
    return 0.5f * x * (1.0f + erff(x * 0.70710678118654752f));
}

// ---------------------------------------------------------------------------
// Gather -> fp16 flat: flat[r, g*512+e] = fp16(emb[tok(s-2+g, b), e])
// One thread handles 8 consecutive elements (2 float4 reads, 1 16B write).
// ---------------------------------------------------------------------------
__global__ void gather_f16(const int* __restrict__ tokens, const float* __restrict__ emb) {
    int idx = blockIdx.x * blockDim.x + threadIdx.x;   // one 8-elem chunk
    const int Q = K1 / 8;                               // 192 per row
    if (idx >= MROWS * Q) return;
    int r = idx / Q;
    int q = idx - r * Q;
    int s = r >> 2;
    int b = r & 3;
    int g = q / (EMBED / 8);
    int e8 = q - g * (EMBED / 8);
    int pos = s + g - (KCTX - 1);
    int tok = (pos >= 0) ? tokens[pos * BATCH + b] : 0;
    const float4* src = reinterpret_cast<const float4*>(emb + (size_t)tok * EMBED) + e8 * 2;
    float4 v0 = src[0];
    float4 v1 = src[1];
    struct alignas(16) H8 { __half2 a, b, c, d; } o;
    o.a = __floats2half2_rn(v0.x, v0.y);
    o.b = __floats2half2_rn(v0.z, v0.w);
    o.c = __floats2half2_rn(v1.x, v1.y);
    o.d = __floats2half2_rn(v1.z, v1.w);
    reinterpret_cast<H8*>(g_flat)[idx] = o;
}

// ---------------------------------------------------------------------------
// Transpose + fp16: W[R][C] -> T[C][R]
// ---------------------------------------------------------------------------
__global__ void transpose_f16(const float* __restrict__ W, __half* __restrict__ T,
                              int R, int C) {
    __shared__ float t[32][33];
    int c = blockIdx.x * 32 + threadIdx.x;
    int r = blockIdx.y * 32 + threadIdx.y;
    t[threadIdx.y][threadIdx.x] = W[(size_t)r * C + c];
    __syncthreads();
    int c2 = blockIdx.x * 32 + threadIdx.y;
    int r2 = blockIdx.y * 32 + threadIdx.x;
    T[(size_t)c2 * R + r2] = __float2half_rn(t[threadIdx.x][threadIdx.y]);
}

// ---------------------------------------------------------------------------
// Unified fp16 HMMA GEMM: C[M,N] = A[M,K] @ B[N,K]^T (+bias, opt GELU)
// BK=64, 144B-stride smem rows (conflict-free ldmatrix), 3-stage cp.async.
// Warp tile = (BMt/WM) x (BN_/WN).
// EPI=0: out fp32 = acc + bias.    EPI=1: out fp16 = gelu(acc + bias).
// ---------------------------------------------------------------------------
#define RSB2 144   // 64 halves (128B) + 16B pad

template <int KD, int BMt, int BN_, int WM, int WN, int EPI>
__global__ void __launch_bounds__(32 * WM * WN, 1)
gemm16(const __half* __restrict__ A, const __half* __restrict__ Bt,
       const float* __restrict__ bias, void* __restrict__ outp, int N) {
    extern __shared__ char smem[];
    constexpr int NT    = 32 * WM * WN;
    constexpr int WROWS = BMt / WM;
    constexpr int WCOLS = BN_ / WN;
    constexpr int MFR   = WROWS / 16;
    constexpr int NFR   = WCOLS / 8;
    constexpr int ROWS  = BMt + BN_;
    constexpr int STAGE = ROWS * RSB2;
    constexpr int NKB   = KD / 64;
    constexpr int NCP   = ROWS * 8 / NT;   // cp16 per thread per stage

    uint32_t sb = smem_u32(smem);
    int tid = threadIdx.x;
    int wid = tid >> 5;
    int lane = tid & 31;
    int warp_m = wid % WM;
    int warp_n = wid / WM;
    int bm = blockIdx.x * BMt;
    int bn = blockIdx.y * BN_;

    float acc[MFR][NFR][4];
#pragma unroll
    for (int i = 0; i < MFR; i++)
#pragma unroll
        for (int j = 0; j < NFR; j++)
#pragma unroll
            for (int r = 0; r < 4; r++) acc[i][j][r] = 0.0f;

    auto issue = [&](int kb) {
        int s = kb % 3;
        int koff = kb * 64;
        uint32_t base = sb + s * STAGE;
#pragma unroll
        for (int i = 0; i < NCP; i++) {
            int li = tid + i * NT;
            int r = li >> 3;                 // stage row
            int ch = li & 7;                 // 16B chunk within 128B
            const __half* src = (r < BMt)
                ? A  + (size_t)(bm + r) * KD + koff + ch * 8
                : Bt + (size_t)(bn + r - BMt) * KD + koff + ch * 8;
            cp16(base + r * RSB2 + ch * 16, src);
        }
        cp_commit();
    };

    issue(0);
    issue(1);

    int lrow = (lane & 7) + ((lane >> 3) & 1) * 8;
    int lkb = (lane >> 4) * 16;
    uint32_t a_off = (uint32_t)(warp_m * WROWS + lrow) * RSB2 + lkb;
    uint32_t b_off = (uint32_t)(BMt + warp_n * WCOLS + lrow) * RSB2 + lkb;

    for (int kb = 0; kb < NKB; kb++) {
        int s = kb % 3;
        asm volatile("cp.async.wait_group 1;\n" ::: "memory");
        __syncthreads();
        if (kb + 2 < NKB) issue(kb + 2);

        uint32_t smA = sb + s * STAGE;
#pragma unroll
        for (int k16 = 0; k16 < 4; k16++) {
            uint32_t ko = k16 * 32;          // 16 halves = 32B per k16
            uint32_t ar[MFR][4];
#pragma unroll
            for (int fm = 0; fm < MFR; fm++)
                LDSM_X4(ar[fm][0], ar[fm][1], ar[fm][2], ar[fm][3],
                        smA + a_off + fm * 16 * RSB2 + ko);
            uint32_t br[NFR][2];
#pragma unroll
            for (int fp = 0; fp < NFR / 2; fp++) {
                uint32_t r0, r1, r2, r3;
                LDSM_X4(r0, r1, r2, r3,
                        smA + b_off + fp * 16 * RSB2 + ko);
                br[2 * fp][0] = r0; br[2 * fp][1] = r2;
                br[2 * fp + 1][0] = r1; br[2 * fp + 1][1] = r3;
            }
#pragma unroll
            for (int fm = 0; fm < MFR; fm++)
#pragma unroll
                for (int fn = 0; fn < NFR; fn++)
                    MMA_F16(acc[fm][fn], ar[fm], br[fn]);
        }
    }

    // ---------------- epilogue ----------------
    int gr = lane >> 2;
    int qc = (lane & 3) * 2;
#pragma unroll
    for (int fm = 0; fm < MFR; fm++) {
        int m0 = bm + warp_m * WROWS + fm * 16 + gr;
#pragma unroll
        for (int fn = 0; fn < NFR; fn++) {
            int c0 = bn + warp_n * WCOLS + fn * 8 + qc;
            float2 bv = *reinterpret_cast<const float2*>(bias + c0);
            float v00 = acc[fm][fn][0] + bv.x;
            float v01 = acc[fm][fn][1] + bv.y;
            float v10 = acc[fm][fn][2] + bv.x;
            float v11 = acc[fm][fn][3] + bv.y;
            if (EPI == 0) {
                float* out = (float*)outp;
                *reinterpret_cast<float2*>(out + (size_t)m0 * N + c0) =
                    make_float2(v00, v01);
                *reinterpret_cast<float2*>(out + (size_t)(m0 + 8) * N + c0) =
                    make_float2(v10, v11);
            } else {
                __half* out = (__half*)outp;
                *reinterpret_cast<__half2*>(out + (size_t)m0 * N + c0) =
                    __floats2half2_rn(gelu_exact(v00), gelu_exact(v01));
                *reinterpret_cast<__half2*>(out + (size_t)(m0 + 8) * N + c0) =
                    __floats2half2_rn(gelu_exact(v10), gelu_exact(v11));
            }
        }
    }
}

using G1 = void(const __half*, const __half*, const float*, void*, int);

#define SMEM_G1 (3 * (128 + 128) * RSB2)   // 110592
#define SMEM_G2 (3 * (256 + 128) * RSB2)   // 165888

// ---------------------------------------------------------------------------
extern "C" void kernel_launch(void* const* d_in, const int* in_sizes, int n_in,
                              void* d_out, int out_size) {
    const int*   tokens = (const int*)  d_in[0];
    const float* emb    = (const float*)d_in[1];
    const float* W1     = (const float*)d_in[2];
    const float* b1     = (const float*)d_in[3];
    const float* W2     = (const float*)d_in[4];
    const float* b2     = (const float*)d_in[5];
    float* out = (float*)d_out;

    __half *fp, *w1t, *w2t, *hp;
    cudaGetSymbolAddress((void**)&fp,  g_flat);
    cudaGetSymbolAddress((void**)&w1t, g_w1t);
    cudaGetSymbolAddress((void**)&w2t, g_w2t);
    cudaGetSymbolAddress((void**)&hp,  g_h);

    cudaFuncSetAttribute((G1*)gemm16<K1, 128, 128, 2, 4, 1>,
                         cudaFuncAttributeMaxDynamicSharedMemorySize, SMEM_G1);
    cudaFuncSetAttribute((G1*)gemm16<HIDDEN, 256, 128, 4, 4, 0>,
                         cudaFuncAttributeMaxDynamicSharedMemorySize, SMEM_G2);

    // 1) gather -> fp16 flat
    {
        int total8 = MROWS * (K1 / 8);
        gather_f16<<<(total8 + 255) / 256, 256>>>(tokens, emb);
    }
    // 2) weight transposes -> fp16 K-major
    {
        dim3 blk(32, 32);
        transpose_f16<<<dim3(HIDDEN / 32, K1 / 32), blk>>>(W1, w1t, K1, HIDDEN);
        transpose_f16<<<dim3(VOCAB / 32, HIDDEN / 32), blk>>>(W2, w2t, HIDDEN, VOCAB);
    }
    // 3) h = fp16(gelu(flat @ W1^T + b1))   (M=8192, N=256, K=1536)
    {
        dim3 grid(MROWS / 128, HIDDEN / 128);   // (64, 2)
        gemm16<K1, 128, 128, 2, 4, 1><<<grid, 256, SMEM_G1>>>(fp, w1t, b1, hp, HIDDEN);
    }
    // 4) logits = h @ W2^T + b2   (M=8192, N=32000, K=256)
    {
        dim3 grid(MROWS / 256, VOCAB / 128);    // (32, 250)
        gemm16<HIDDEN, 256, 128, 4, 4, 0><<<grid, 512, SMEM_G2>>>(hp, w2t, b2, out, VOCAB);
    }
}

// round 10
// speedup vs baseline: 1.0790x; 1.0210x over previous
#include <cuda_runtime.h>
#include <cuda_fp16.h>
#include <math.h>
#include <stdint.h>

#define SEQ    2048
#define BATCH  4
#define KCTX   3
#define EMBED  512
#define HIDDEN 256
#define VOCAB  32000
#define MROWS  (SEQ * BATCH)      // 8192
#define K1     (KCTX * EMBED)     // 1536

// ---------------- scratch (static device globals) ----------------
__device__ __half g_flat[MROWS * K1];      // [8192][1536] fp16
__device__ __half g_w1t[HIDDEN * K1];      // [256][1536] K-major fp16
__device__ __half g_w2t[VOCAB * HIDDEN];   // [32000][256] K-major fp16
__device__ __half g_h[MROWS * HIDDEN];     // [8192][256] fp16

// ---------------- helpers ----------------
__device__ __forceinline__ uint32_t smem_u32(const void* p) {
    uint32_t a;
    asm("{ .reg .u64 t; cvta.to.shared.u64 t, %1; cvt.u32.u64 %0, t; }" : "=r"(a) : "l"(p));
    return a;
}
__device__ __forceinline__ void cp16(uint32_t dst, const void* src) {
    asm volatile("cp.async.cg.shared.global [%0], [%1], 16;\n" :: "r"(dst), "l"(src));
}
__device__ __forceinline__ void cp_commit() { asm volatile("cp.async.commit_group;\n" ::: "memory"); }

#define LDSM_X4(r0, r1, r2, r3, addr) \
    asm volatile("ldmatrix.sync.aligned.m8n8.x4.shared.b16 {%0,%1,%2,%3}, [%4];" \
                 : "=r"(r0), "=r"(r1), "=r"(r2), "=r"(r3) : "r"(addr))

#define MMA_F16(d, a, b) \
    asm volatile("mma.sync.aligned.m16n8k16.row.col.f32.f16.f16.f32 " \
                 "{%0,%1,%2,%3}, {%4,%5,%6,%7}, {%8,%9}, {%0,%1,%2,%3};" \
                 : "+f"((d)[0]), "+f"((d)[1]), "+f"((d)[2]), "+f"((d)[3]) \
                 : "r"((a)[0]), "r"((a)[1]), "r"((a)[2]), "r"((a)[3]), \
                   "r"((b)[0]), "r"((b)[1]))

__device__ __forceinline__ float gelu_exact(float x) {
    return 0.5f * x * (1.0f + erff(x * 0.70710678118654752f));
}

// ---------------------------------------------------------------------------
// Gather -> fp16 flat
// ---------------------------------------------------------------------------
__global__ void gather_f16(const int* __restrict__ tokens, const float* __restrict__ emb) {
    int idx = blockIdx.x * blockDim.x + threadIdx.x;   // one 8-elem chunk
    const int Q = K1 / 8;                               // 192 per row
    if (idx >= MROWS * Q) return;
    int r = idx / Q;
    int q = idx - r * Q;
    int s = r >> 2;
    int b = r & 3;
    int g = q / (EMBED / 8);
    int e8 = q - g * (EMBED / 8);
    int pos = s + g - (KCTX - 1);
    int tok = (pos >= 0) ? tokens[pos * BATCH + b] : 0;
    const float4* src = reinterpret_cast<const float4*>(emb + (size_t)tok * EMBED) + e8 * 2;
    float4 v0 = src[0];
    float4 v1 = src[1];
    struct alignas(16) H8 { __half2 a, b, c, d; } o;
    o.a = __floats2half2_rn(v0.x, v0.y);
    o.b = __floats2half2_rn(v0.z, v0.w);
    o.c = __floats2half2_rn(v1.x, v1.y);
    o.d = __floats2half2_rn(v1.z, v1.w);
    reinterpret_cast<H8*>(g_flat)[idx] = o;
}

// ---------------------------------------------------------------------------
// Transpose + fp16: W[R][C] -> T[C][R]
// ---------------------------------------------------------------------------
__global__ void transpose_f16(const float* __restrict__ W, __half* __restrict__ T,
                              int R, int C) {
    __shared__ float t[32][33];
    int c = blockIdx.x * 32 + threadIdx.x;
    int r = blockIdx.y * 32 + threadIdx.y;
    t[threadIdx.y][threadIdx.x] = W[(size_t)r * C + c];
    __syncthreads();
    int c2 = blockIdx.x * 32 + threadIdx.y;
    int r2 = blockIdx.y * 32 + threadIdx.x;
    T[(size_t)c2 * R + r2] = __float2half_rn(t[threadIdx.x][threadIdx.y]);
}

// ---------------------------------------------------------------------------
// Unified fp16 HMMA GEMM: C[M,N] = A[M,K] @ B[N,K]^T (+bias, opt GELU)
// BK=64, 144B-stride smem rows, 3-stage cp.async, minBlocks=2 for occupancy.
// EPI=0: out fp32 = acc + bias.    EPI=1: out fp16 = gelu(acc + bias).
// ---------------------------------------------------------------------------
#define RSB2 144   // 64 halves (128B) + 16B pad

template <int KD, int BMt, int BN_, int WM, int WN, int EPI>
__global__ void __launch_bounds__(32 * WM * WN, 2)
gemm16(const __half* __restrict__ A, const __half* __restrict__ Bt,
       const float* __restrict__ bias, void* __restrict__ outp, int N) {
    extern __shared__ char smem[];
    constexpr int NT    = 32 * WM * WN;
    constexpr int WROWS = BMt / WM;
    constexpr int WCOLS = BN_ / WN;
    constexpr int MFR   = WROWS / 16;
    constexpr int NFR   = WCOLS / 8;
    constexpr int ROWS  = BMt + BN_;
    constexpr int STAGE = ROWS * RSB2;
    constexpr int NKB   = KD / 64;
    constexpr int NCP   = ROWS * 8 / NT;   // cp16 per thread per stage

    uint32_t sb = smem_u32(smem);
    int tid = threadIdx.x;
    int wid = tid >> 5;
    int lane = tid & 31;
    int warp_m = wid % WM;
    int warp_n = wid / WM;
    int bm = blockIdx.x * BMt;
    int bn = blockIdx.y * BN_;

    float acc[MFR][NFR][4];
#pragma unroll
    for (int i = 0; i < MFR; i++)
#pragma unroll
        for (int j = 0; j < NFR; j++)
#pragma unroll
            for (int r = 0; r < 4; r++) acc[i][j][r] = 0.0f;

    auto issue = [&](int kb) {
        int s = kb % 3;
        int koff = kb * 64;
        uint32_t base = sb + s * STAGE;
#pragma unroll
        for (int i = 0; i < NCP; i++) {
            int li = tid + i * NT;
            int r = li >> 3;                 // stage row
            int ch = li & 7;                 // 16B chunk within 128B
            const __half* src = (r < BMt)
                ? A  + (size_t)(bm + r) * KD + koff + ch * 8
                : Bt + (size_t)(bn + r - BMt) * KD + koff + ch * 8;
            cp16(base + r * RSB2 + ch * 16, src);
        }
        cp_commit();
    };

    issue(0);
    issue(1);

    int lrow = (lane & 7) + ((lane >> 3) & 1) * 8;
    int lkb = (lane >> 4) * 16;
    uint32_t a_off = (uint32_t)(warp_m * WROWS + lrow) * RSB2 + lkb;
    uint32_t b_off = (uint32_t)(BMt + warp_n * WCOLS + lrow) * RSB2 + lkb;

    for (int kb = 0; kb < NKB; kb++) {
        int s = kb % 3;
        asm volatile("cp.async.wait_group 1;\n" ::: "memory");
        __syncthreads();
        if (kb + 2 < NKB) issue(kb + 2);

        uint32_t smA = sb + s * STAGE;
#pragma unroll
        for (int k16 = 0; k16 < 4; k16++) {
            uint32_t ko = k16 * 32;          // 16 halves = 32B per k16
            uint32_t ar[MFR][4];
#pragma unroll
            for (int fm = 0; fm < MFR; fm++)
                LDSM_X4(ar[fm][0], ar[fm][1], ar[fm][2], ar[fm][3],
                        smA + a_off + fm * 16 * RSB2 + ko);
            uint32_t br[NFR][2];
#pragma unroll
            for (int fp = 0; fp < NFR / 2; fp++) {
                uint32_t r0, r1, r2, r3;
                LDSM_X4(r0, r1, r2, r3,
                        smA + b_off + fp * 16 * RSB2 + ko);
                br[2 * fp][0] = r0; br[2 * fp][1] = r2;
                br[2 * fp + 1][0] = r1; br[2 * fp + 1][1] = r3;
            }
#pragma unroll
            for (int fm = 0; fm < MFR; fm++)
#pragma unroll
                for (int fn = 0; fn < NFR; fn++)
                    MMA_F16(acc[fm][fn], ar[fm], br[fn]);
        }
    }

    // ---------------- epilogue ----------------
    int gr = lane >> 2;
    int qc = (lane & 3) * 2;
#pragma unroll
    for (int fm = 0; fm < MFR; fm++) {
        int m0 = bm + warp_m * WROWS + fm * 16 + gr;
#pragma unroll
        for (int fn = 0; fn < NFR; fn++) {
            int c0 = bn + warp_n * WCOLS + fn * 8 + qc;
            float2 bv = *reinterpret_cast<const float2*>(bias + c0);
            float v00 = acc[fm][fn][0] + bv.x;
            float v01 = acc[fm][fn][1] + bv.y;
            float v10 = acc[fm][fn][2] + bv.x;
            float v11 = acc[fm][fn][3] + bv.y;
            if (EPI == 0) {
                float* out = (float*)outp;
                *reinterpret_cast<float2*>(out + (size_t)m0 * N + c0) =
                    make_float2(v00, v01);
                *reinterpret_cast<float2*>(out + (size_t)(m0 + 8) * N + c0) =
                    make_float2(v10, v11);
            } else {
                __half* out = (__half*)outp;
                *reinterpret_cast<__half2*>(out + (size_t)m0 * N + c0) =
                    __floats2half2_rn(gelu_exact(v00), gelu_exact(v01));
                *reinterpret_cast<__half2*>(out + (size_t)(m0 + 8) * N + c0) =
                    __floats2half2_rn(gelu_exact(v10), gelu_exact(v11));
            }
        }
    }
}

using G1 = void(const __half*, const __half*, const float*, void*, int);

#define SMEM_G1 (3 * (64 + 128) * RSB2)    // 82944
#define SMEM_G2 (3 * (128 + 128) * RSB2)   // 110592

// ---------------------------------------------------------------------------
extern "C" void kernel_launch(void* const* d_in, const int* in_sizes, int n_in,
                              void* d_out, int out_size) {
    const int*   tokens = (const int*)  d_in[0];
    const float* emb    = (const float*)d_in[1];
    const float* W1     = (const float*)d_in[2];
    const float* b1     = (const float*)d_in[3];
    const float* W2     = (const float*)d_in[4];
    const float* b2     = (const float*)d_in[5];
    float* out = (float*)d_out;

    __half *fp, *w1t, *w2t, *hp;
    cudaGetSymbolAddress((void**)&fp,  g_flat);
    cudaGetSymbolAddress((void**)&w1t, g_w1t);
    cudaGetSymbolAddress((void**)&w2t, g_w2t);
    cudaGetSymbolAddress((void**)&hp,  g_h);

    // GEMM1: BM=64, BN=128, 8 warps (2x4), warp tile 32x32 -> 2+ CTAs/SM
    cudaFuncSetAttribute((G1*)gemm16<K1, 64, 128, 2, 4, 1>,
                         cudaFuncAttributeMaxDynamicSharedMemorySize, SMEM_G1);
    // GEMM2: BM=128, BN=128, 8 warps (2x4), warp tile 64x32 -> 2 CTAs/SM
    cudaFuncSetAttribute((G1*)gemm16<HIDDEN, 128, 128, 2, 4, 0>,
                         cudaFuncAttributeMaxDynamicSharedMemorySize, SMEM_G2);

    // 1) gather -> fp16 flat
    {
        int total8 = MROWS * (K1 / 8);
        gather_f16<<<(total8 + 255) / 256, 256>>>(tokens, emb);
    }
    // 2) weight transposes -> fp16 K-major
    {
        dim3 blk(32, 32);
        transpose_f16<<<dim3(HIDDEN / 32, K1 / 32), blk>>>(W1, w1t, K1, HIDDEN);
        transpose_f16<<<dim3(VOCAB / 32, HIDDEN / 32), blk>>>(W2, w2t, HIDDEN, VOCAB);
    }
    // 3) h = fp16(gelu(flat @ W1^T + b1))   (M=8192, N=256, K=1536)
    {
        dim3 grid(MROWS / 64, HIDDEN / 128);    // (128, 2) = 256 CTAs
        gemm16<K1, 64, 128, 2, 4, 1><<<grid, 256, SMEM_G1>>>(fp, w1t, b1, hp, HIDDEN);
    }
    // 4) logits = h @ W2^T + b2   (M=8192, N=32000, K=256)
    {
        dim3 grid(MROWS / 128, VOCAB / 128);    // (64, 250) = 16000 CTAs
        gemm16<HIDDEN, 128, 128, 2, 4, 0><<<grid, 256, SMEM_G2>>>(hp, w2t, b2, out, VOCAB);
    }
}